// round 4
// baseline (speedup 1.0000x reference)
#include <cuda_runtime.h>
#include <cuda_bf16.h>
#include <mma.h>
#include <math.h>
#include <stdint.h>

// ---------------- model constants ----------------
#define D_MODEL 768
#define N_LAYER 4
#define D_STATE 16
#define D_CONV 4
#define DT_RANK 48
#define D_INNER 1536
#define B_SZ 2
#define L_SEQ 1024
#define N_MELS 80
#define M_ROWS (B_SZ * L_SEQ)              // 2048
#define XDBL_COLS (DT_RANK + 2 * D_STATE)  // 80

// ---------------- scratch (device globals; no runtime alloc) ----------------
__device__ float g_x[M_ROWS * D_MODEL];
__device__ float g_h[M_ROWS * D_MODEL];
__device__ float g_xz[M_ROWS * 2 * D_INNER];
__device__ float g_xi[M_ROWS * D_INNER];
__device__ float g_xdbl[M_ROWS * XDBL_COLS];
__device__ float g_delta[M_ROWS * D_INNER];
__device__ float g_y[M_ROWS * D_INNER];

__device__ __forceinline__ void split_bf16(float v, uint16_t& hi, uint16_t& lo) {
    __nv_bfloat16 h = __float2bfloat16(v);
    float r = v - __bfloat162float(h);
    __nv_bfloat16 l = __float2bfloat16(r);
    hi = __nv_bfloat16_raw(h).x;
    lo = __nv_bfloat16_raw(l).x;
}

// ---------------- WMMA split-bf16 GEMM ----------------
// C[M,N] = A[M,K] * B[K,N], fp32 in/out. Block 128x128, BK=32, 8 warps.
// Split: A=Ah+Al, B=Bh+Bl (bf16); acc += Ah*Bh + Ah*Bl + Al*Bh (fp32 acc).
__global__ __launch_bounds__(256, 2)
void wmma_gemm(int M, int N, int K,
               const float* __restrict__ A, int lda,
               const float* __restrict__ B, int ldb,
               float* __restrict__ C, int ldc)
{
    using namespace nvcuda;
    constexpr int SA = 40;    // padded stride (elements) for 32-wide A rows
    constexpr int SB = 136;   // padded stride for 128-wide B rows
    __shared__ __nv_bfloat16 sAh[128 * SA], sAl[128 * SA];
    __shared__ __nv_bfloat16 sBh[32 * SB],  sBl[32 * SB];

    const int t    = threadIdx.x;
    const int warp = t >> 5;
    const int wm   = warp >> 2;   // 0..1  (64 rows each)
    const int wn   = warp & 3;    // 0..3  (32 cols each)
    const int row0 = blockIdx.y * 128;
    const int col0 = blockIdx.x * 128;

    wmma::fragment<wmma::accumulator, 16, 16, 16, float> acc[4][2];
#pragma unroll
    for (int i = 0; i < 4; i++)
#pragma unroll
        for (int j = 0; j < 2; j++) wmma::fill_fragment(acc[i][j], 0.0f);

    const int ar = t >> 4;          // A: base row (16 rows / pass)
    const int ak = (t & 15) * 2;    // A: k pair
    const int bk = t >> 6;          // B: base k row (4 rows / pass)
    const int bn = (t & 63) * 2;    // B: n pair

    float2 ra[8], rb[8];
    const int KT = (K + 31) / 32;

    // ---- prefetch chunk 0 ----
    {
        const int k0 = 0;
#pragma unroll
        for (int p = 0; p < 8; p++) {
            int gm = row0 + ar + p * 16;
            int gk = k0 + ak;
            float2 v = make_float2(0.f, 0.f);
            if (gk + 1 < K)      v = *(const float2*)(A + (long)gm * lda + gk);
            else if (gk < K)     v.x = A[(long)gm * lda + gk];
            ra[p] = v;
        }
#pragma unroll
        for (int p = 0; p < 8; p++) {
            int gk = k0 + bk + p * 4;
            int gn = col0 + bn;
            float2 v = make_float2(0.f, 0.f);
            if (gk < K) {
                if (gn + 1 < N)  v = *(const float2*)(B + (long)gk * ldb + gn);
                else if (gn < N) v.x = B[(long)gk * ldb + gn];
            }
            rb[p] = v;
        }
    }

    for (int kt = 0; kt < KT; kt++) {
        __syncthreads();   // previous compute done before overwriting smem
        // ---- store prefetched chunk to smem (split bf16) ----
#pragma unroll
        for (int p = 0; p < 8; p++) {
            int r = ar + p * 16;
            uint16_t h0, l0, h1, l1;
            split_bf16(ra[p].x, h0, l0);
            split_bf16(ra[p].y, h1, l1);
            *(uint32_t*)&sAh[r * SA + ak] = (uint32_t)h0 | ((uint32_t)h1 << 16);
            *(uint32_t*)&sAl[r * SA + ak] = (uint32_t)l0 | ((uint32_t)l1 << 16);
        }
#pragma unroll
        for (int p = 0; p < 8; p++) {
            int k = bk + p * 4;
            uint16_t h0, l0, h1, l1;
            split_bf16(rb[p].x, h0, l0);
            split_bf16(rb[p].y, h1, l1);
            *(uint32_t*)&sBh[k * SB + bn] = (uint32_t)h0 | ((uint32_t)h1 << 16);
            *(uint32_t*)&sBl[k * SB + bn] = (uint32_t)l0 | ((uint32_t)l1 << 16);
        }
        __syncthreads();

        // ---- prefetch next chunk (LDGs overlap with compute below) ----
        if (kt + 1 < KT) {
            const int k0 = (kt + 1) * 32;
#pragma unroll
            for (int p = 0; p < 8; p++) {
                int gm = row0 + ar + p * 16;
                int gk = k0 + ak;
                float2 v = make_float2(0.f, 0.f);
                if (gk + 1 < K)      v = *(const float2*)(A + (long)gm * lda + gk);
                else if (gk < K)     v.x = A[(long)gm * lda + gk];
                ra[p] = v;
            }
#pragma unroll
            for (int p = 0; p < 8; p++) {
                int gk = k0 + bk + p * 4;
                int gn = col0 + bn;
                float2 v = make_float2(0.f, 0.f);
                if (gk < K) {
                    if (gn + 1 < N)  v = *(const float2*)(B + (long)gk * ldb + gn);
                    else if (gn < N) v.x = B[(long)gk * ldb + gn];
                }
                rb[p] = v;
            }
        }

        // ---- compute: 2 k-steps of 16 ----
#pragma unroll
        for (int ks = 0; ks < 2; ks++) {
#pragma unroll
            for (int j = 0; j < 2; j++) {
                wmma::fragment<wmma::matrix_b, 16, 16, 16, __nv_bfloat16, wmma::row_major> fbh, fbl;
                wmma::load_matrix_sync(fbh, &sBh[(ks * 16) * SB + wn * 32 + j * 16], SB);
                wmma::load_matrix_sync(fbl, &sBl[(ks * 16) * SB + wn * 32 + j * 16], SB);
#pragma unroll
                for (int i = 0; i < 4; i++) {
                    wmma::fragment<wmma::matrix_a, 16, 16, 16, __nv_bfloat16, wmma::row_major> fah, fal;
                    wmma::load_matrix_sync(fah, &sAh[(wm * 64 + i * 16) * SA + ks * 16], SA);
                    wmma::load_matrix_sync(fal, &sAl[(wm * 64 + i * 16) * SA + ks * 16], SA);
                    wmma::mma_sync(acc[i][j], fah, fbh, acc[i][j]);
                    wmma::mma_sync(acc[i][j], fah, fbl, acc[i][j]);
                    wmma::mma_sync(acc[i][j], fal, fbh, acc[i][j]);
                }
            }
        }
    }

    // ---- epilogue: direct global stores, fragment-granularity N guard ----
#pragma unroll
    for (int i = 0; i < 4; i++)
#pragma unroll
        for (int j = 0; j < 2; j++) {
            int gm = row0 + wm * 64 + i * 16;
            int gn = col0 + wn * 32 + j * 16;
            if (gn + 16 <= N)
                wmma::store_matrix_sync(C + (long)gm * ldc + gn, acc[i][j],
                                        ldc, wmma::mem_row_major);
        }
}

// ---------------- elementwise / small kernels ----------------
__global__ void embed_kernel(const int* __restrict__ ids,
                             const float* __restrict__ emb)
{
    int row = blockIdx.x;
    int id = ids[row];
    for (int c = threadIdx.x; c < D_MODEL; c += blockDim.x)
        g_x[row * D_MODEL + c] = emb[(long)id * D_MODEL + c];
}

__global__ void rmsnorm_kernel(const float* __restrict__ x,
                               const float* __restrict__ w,
                               float* __restrict__ out)
{
    __shared__ float red[256];
    int row = blockIdx.x;
    const float* xr = x + row * D_MODEL;
    float s = 0.0f;
    for (int c = threadIdx.x; c < D_MODEL; c += blockDim.x) {
        float v = xr[c];
        s += v * v;
    }
    red[threadIdx.x] = s;
    __syncthreads();
    for (int off = 128; off > 0; off >>= 1) {
        if (threadIdx.x < off) red[threadIdx.x] += red[threadIdx.x + off];
        __syncthreads();
    }
    float scale = rsqrtf(red[0] / (float)D_MODEL + 1e-5f);
    for (int c = threadIdx.x; c < D_MODEL; c += blockDim.x)
        out[row * D_MODEL + c] = xr[c] * scale * w[c];
}

__global__ void conv_silu_kernel(const float* __restrict__ cw,
                                 const float* __restrict__ cb)
{
    int i = blockIdx.x * blockDim.x + threadIdx.x;
    if (i >= M_ROWS * D_INNER) return;
    int row = i / D_INNER;
    int d = i % D_INNER;
    int b = row / L_SEQ;
    int l = row % L_SEQ;
    float acc = cb[d];
#pragma unroll
    for (int k = 0; k < D_CONV; k++) {
        int ll = l + k - (D_CONV - 1);
        if (ll >= 0)
            acc = fmaf(g_xz[(long)(b * L_SEQ + ll) * (2 * D_INNER) + d],
                       cw[d * D_CONV + k], acc);
    }
    float sg = 1.0f / (1.0f + __expf(-acc));
    g_xi[i] = acc * sg;
}

__global__ void bias_softplus_kernel(const float* __restrict__ bias)
{
    int i = blockIdx.x * blockDim.x + threadIdx.x;
    if (i >= M_ROWS * D_INNER) return;
    int d = i % D_INNER;
    float v = g_delta[i] + bias[d];
    float r = (v > 30.0f) ? v : log1pf(__expf(v));
    g_delta[i] = r;
}

__global__ void residual_add_kernel(void)
{
    int i = blockIdx.x * blockDim.x + threadIdx.x;
    if (i < M_ROWS * D_MODEL) g_x[i] += g_h[i];
}

// ---------------- selective scan (matches reference numerics) ----------------
__global__ __launch_bounds__(256)
void scan_kernel(const float* __restrict__ A_log,
                 const float* __restrict__ Dp)
{
    int tid = threadIdx.x;
    int warp = tid >> 5;
    int lane = tid & 31;
    int half = lane >> 4;
    int n = lane & 15;

    int ch = blockIdx.x * 16 + warp * 2 + half;
    int b = ch / D_INNER;
    int d = ch % D_INNER;

    float A_dn = -__expf(A_log[d * D_STATE + n]);
    float Dd = Dp[d];

    float s = 0.0f, P = 0.0f;
    long rowbase = (long)b * L_SEQ;

    for (int l = 0; l < L_SEQ; l++) {
        long row = rowbase + l;
        float dt = g_delta[row * D_INNER + d];
        float u  = g_xi[row * D_INNER + d];
        float Bn = g_xdbl[row * XDBL_COLS + DT_RANK + n];
        float Cn = g_xdbl[row * XDBL_COLS + DT_RANK + D_STATE + n];

        if (l > 0) s += fmaxf(dt * A_dn, -20.0f);
        float e = __expf(s);
        P += __fdividef(dt * u * Bn, e + 1e-12f);
        float x = P * e;
        float yp = x * Cn;

#pragma unroll
        for (int off = 8; off >= 1; off >>= 1)
            yp += __shfl_xor_sync(0xffffffffu, yp, off, 16);

        if (n == 0) {
            float yv = yp + u * Dd;
            float r = g_xz[row * (2 * D_INNER) + D_INNER + d];
            float sr = r / (1.0f + __expf(-r));
            g_y[row * D_INNER + d] = yv * sr;
        }
    }
}

// ---------------- host side ----------------
static inline void* sym(const void* s)
{
    void* p = nullptr;
    cudaGetSymbolAddress(&p, s);
    return p;
}

extern "C" void kernel_launch(void* const* d_in, const int* in_sizes, int n_in,
                              void* d_out, int out_size)
{
    const int*   input_ids = (const int*)  d_in[0];
    const float* embedding = (const float*)d_in[1];
    const float* rms_w     = (const float*)d_in[2];
    const float* in_proj_w = (const float*)d_in[3];
    const float* conv_w    = (const float*)d_in[4];
    const float* conv_b    = (const float*)d_in[5];
    const float* x_proj_w  = (const float*)d_in[6];
    const float* dt_proj_w = (const float*)d_in[7];
    const float* dt_proj_b = (const float*)d_in[8];
    const float* A_log     = (const float*)d_in[9];
    const float* D_param   = (const float*)d_in[10];
    const float* out_proj_w= (const float*)d_in[11];
    const float* norm_f_w  = (const float*)d_in[12];
    const float* head_w    = (const float*)d_in[13];
    float* out = (float*)d_out;

    float* px     = (float*)sym(g_x);
    float* ph     = (float*)sym(g_h);
    float* pxz    = (float*)sym(g_xz);
    float* pxi    = (float*)sym(g_xi);
    float* pxdbl  = (float*)sym(g_xdbl);
    float* pdelta = (float*)sym(g_delta);
    float* py     = (float*)sym(g_y);

    embed_kernel<<<M_ROWS, 256>>>(input_ids, embedding);

    for (int i = 0; i < N_LAYER; i++) {
        const float* rw  = rms_w     + (long)i * D_MODEL;
        const float* iw  = in_proj_w + (long)i * D_MODEL * 2 * D_INNER;
        const float* cw  = conv_w    + (long)i * D_INNER * D_CONV;
        const float* cb  = conv_b    + (long)i * D_INNER;
        const float* xpw = x_proj_w  + (long)i * D_INNER * XDBL_COLS;
        const float* dtw = dt_proj_w + (long)i * DT_RANK * D_INNER;
        const float* dtb = dt_proj_b + (long)i * D_INNER;
        const float* al  = A_log     + (long)i * D_INNER * D_STATE;
        const float* dp  = D_param   + (long)i * D_INNER;
        const float* ow  = out_proj_w+ (long)i * D_INNER * D_MODEL;

        // 1. h = rmsnorm(x)
        rmsnorm_kernel<<<M_ROWS, 256>>>(px, rw, ph);

        // 2. xz = h @ in_w  [2048 x 3072 x 768]
        wmma_gemm<<<dim3(2 * D_INNER / 128, M_ROWS / 128), 256>>>(
            M_ROWS, 2 * D_INNER, D_MODEL, ph, D_MODEL, iw, 2 * D_INNER,
            pxz, 2 * D_INNER);

        // 3. xi = silu(conv(xz[:, :1536]))
        conv_silu_kernel<<<(M_ROWS * D_INNER + 255) / 256, 256>>>(cw, cb);

        // 4. x_dbl = xi @ xp_w  [2048 x 80 x 1536]
        wmma_gemm<<<dim3(1, M_ROWS / 128), 256>>>(
            M_ROWS, XDBL_COLS, D_INNER, pxi, D_INNER, xpw, XDBL_COLS,
            pxdbl, XDBL_COLS);

        // 5. delta_raw = x_dbl[:, :48] @ dt_w  [2048 x 1536 x 48]
        wmma_gemm<<<dim3(D_INNER / 128, M_ROWS / 128), 256>>>(
            M_ROWS, D_INNER, DT_RANK, pxdbl, XDBL_COLS, dtw, D_INNER,
            pdelta, D_INNER);

        // 6. delta = softplus(delta_raw + dt_b)
        bias_softplus_kernel<<<(M_ROWS * D_INNER + 255) / 256, 256>>>(dtb);

        // 7. selective scan + gating -> g_y
        scan_kernel<<<(B_SZ * D_INNER) / 16, 256>>>(al, dp);

        // 8. h_tmp = y @ out_w  [2048 x 768 x 1536]
        wmma_gemm<<<dim3(D_MODEL / 128, M_ROWS / 128), 256>>>(
            M_ROWS, D_MODEL, D_INNER, py, D_INNER, ow, D_MODEL,
            ph, D_MODEL);

        // 9. x += h_tmp
        residual_add_kernel<<<(M_ROWS * D_MODEL + 255) / 256, 256>>>();
    }

    // final rmsnorm + head
    rmsnorm_kernel<<<M_ROWS, 256>>>(px, norm_f_w, ph);
    wmma_gemm<<<dim3(1, M_ROWS / 128), 256>>>(
        M_ROWS, N_MELS, D_MODEL, ph, D_MODEL, head_w, N_MELS,
        out, N_MELS);
}

// round 5
// speedup vs baseline: 2.3443x; 2.3443x over previous
#include <cuda_runtime.h>
#include <cuda_bf16.h>
#include <mma.h>
#include <math.h>
#include <stdint.h>

// ---------------- model constants ----------------
#define D_MODEL 768
#define N_LAYER 4
#define D_STATE 16
#define D_CONV 4
#define DT_RANK 48
#define D_INNER 1536
#define B_SZ 2
#define L_SEQ 1024
#define N_MELS 80
#define M_ROWS (B_SZ * L_SEQ)              // 2048
#define XDBL_COLS (DT_RANK + 2 * D_STATE)  // 80

// ---------------- scratch (device globals; no runtime alloc) ----------------
__device__ float g_x[M_ROWS * D_MODEL];
__device__ float g_h[M_ROWS * D_MODEL];
__device__ float g_xz[M_ROWS * 2 * D_INNER];
__device__ float g_xi[M_ROWS * D_INNER];
__device__ float g_xdbl[M_ROWS * XDBL_COLS];
__device__ float g_delta[M_ROWS * D_INNER];
__device__ float g_y[M_ROWS * D_INNER];

__device__ __forceinline__ void split_bf16(float v, uint16_t& hi, uint16_t& lo) {
    __nv_bfloat16 h = __float2bfloat16(v);
    float r = v - __bfloat162float(h);
    __nv_bfloat16 l = __float2bfloat16(r);
    hi = __nv_bfloat16_raw(h).x;
    lo = __nv_bfloat16_raw(l).x;
}

// ---------------- WMMA split-bf16 GEMM ----------------
// C[M,N] = A[M,K] * B[K,N], fp32 in/out. Block 128x128, BK=32, 8 warps.
// Split: A=Ah+Al, B=Bh+Bl (bf16); acc += Ah*Bh + Ah*Bl + Al*Bh (fp32 acc).
// launch_bounds(256,1): full 255-reg budget -> no spills in MMA mainloop.
__global__ __launch_bounds__(256, 1)
void wmma_gemm(int M, int N, int K,
               const float* __restrict__ A, int lda,
               const float* __restrict__ B, int ldb,
               float* __restrict__ C, int ldc)
{
    using namespace nvcuda;
    constexpr int SA = 40;    // padded stride (elements) for 32-wide A rows
    constexpr int SB = 136;   // padded stride for 128-wide B rows
    __shared__ __nv_bfloat16 sAh[128 * SA], sAl[128 * SA];
    __shared__ __nv_bfloat16 sBh[32 * SB],  sBl[32 * SB];

    const int t    = threadIdx.x;
    const int warp = t >> 5;
    const int wm   = warp >> 2;   // 0..1  (64 rows each)
    const int wn   = warp & 3;    // 0..3  (32 cols each)
    const int row0 = blockIdx.y * 128;
    const int col0 = blockIdx.x * 128;

    wmma::fragment<wmma::accumulator, 16, 16, 16, float> acc[4][2];
#pragma unroll
    for (int i = 0; i < 4; i++)
#pragma unroll
        for (int j = 0; j < 2; j++) wmma::fill_fragment(acc[i][j], 0.0f);

    const int ar = t >> 4;          // A: base row (16 rows / pass)
    const int ak = (t & 15) * 2;    // A: k pair
    const int bk = t >> 6;          // B: base k row (4 rows / pass)
    const int bn = (t & 63) * 2;    // B: n pair

    float2 ra[8], rb[8];
    const int KT = (K + 31) / 32;

    // ---- prefetch chunk 0 ----
    {
        const int k0 = 0;
#pragma unroll
        for (int p = 0; p < 8; p++) {
            int gm = row0 + ar + p * 16;
            int gk = k0 + ak;
            float2 v = make_float2(0.f, 0.f);
            if (gk + 1 < K)      v = *(const float2*)(A + (long)gm * lda + gk);
            else if (gk < K)     v.x = A[(long)gm * lda + gk];
            ra[p] = v;
        }
#pragma unroll
        for (int p = 0; p < 8; p++) {
            int gk = k0 + bk + p * 4;
            int gn = col0 + bn;
            float2 v = make_float2(0.f, 0.f);
            if (gk < K) {
                if (gn + 1 < N)  v = *(const float2*)(B + (long)gk * ldb + gn);
                else if (gn < N) v.x = B[(long)gk * ldb + gn];
            }
            rb[p] = v;
        }
    }

    for (int kt = 0; kt < KT; kt++) {
        __syncthreads();   // previous compute done before overwriting smem
        // ---- store prefetched chunk to smem (split bf16) ----
#pragma unroll
        for (int p = 0; p < 8; p++) {
            int r = ar + p * 16;
            uint16_t h0, l0, h1, l1;
            split_bf16(ra[p].x, h0, l0);
            split_bf16(ra[p].y, h1, l1);
            *(uint32_t*)&sAh[r * SA + ak] = (uint32_t)h0 | ((uint32_t)h1 << 16);
            *(uint32_t*)&sAl[r * SA + ak] = (uint32_t)l0 | ((uint32_t)l1 << 16);
        }
#pragma unroll
        for (int p = 0; p < 8; p++) {
            int k = bk + p * 4;
            uint16_t h0, l0, h1, l1;
            split_bf16(rb[p].x, h0, l0);
            split_bf16(rb[p].y, h1, l1);
            *(uint32_t*)&sBh[k * SB + bn] = (uint32_t)h0 | ((uint32_t)h1 << 16);
            *(uint32_t*)&sBl[k * SB + bn] = (uint32_t)l0 | ((uint32_t)l1 << 16);
        }
        __syncthreads();

        // ---- prefetch next chunk (LDGs overlap with compute below) ----
        if (kt + 1 < KT) {
            const int k0 = (kt + 1) * 32;
#pragma unroll
            for (int p = 0; p < 8; p++) {
                int gm = row0 + ar + p * 16;
                int gk = k0 + ak;
                float2 v = make_float2(0.f, 0.f);
                if (gk + 1 < K)      v = *(const float2*)(A + (long)gm * lda + gk);
                else if (gk < K)     v.x = A[(long)gm * lda + gk];
                ra[p] = v;
            }
#pragma unroll
            for (int p = 0; p < 8; p++) {
                int gk = k0 + bk + p * 4;
                int gn = col0 + bn;
                float2 v = make_float2(0.f, 0.f);
                if (gk < K) {
                    if (gn + 1 < N)  v = *(const float2*)(B + (long)gk * ldb + gn);
                    else if (gn < N) v.x = B[(long)gk * ldb + gn];
                }
                rb[p] = v;
            }
        }

        // ---- compute: 2 k-steps of 16; B frags hoisted per ks, A per i ----
#pragma unroll
        for (int ks = 0; ks < 2; ks++) {
            wmma::fragment<wmma::matrix_b, 16, 16, 16, __nv_bfloat16, wmma::row_major> fbh[2], fbl[2];
#pragma unroll
            for (int j = 0; j < 2; j++) {
                wmma::load_matrix_sync(fbh[j], &sBh[(ks * 16) * SB + wn * 32 + j * 16], SB);
                wmma::load_matrix_sync(fbl[j], &sBl[(ks * 16) * SB + wn * 32 + j * 16], SB);
            }
#pragma unroll
            for (int i = 0; i < 4; i++) {
                wmma::fragment<wmma::matrix_a, 16, 16, 16, __nv_bfloat16, wmma::row_major> fah, fal;
                wmma::load_matrix_sync(fah, &sAh[(wm * 64 + i * 16) * SA + ks * 16], SA);
                wmma::load_matrix_sync(fal, &sAl[(wm * 64 + i * 16) * SA + ks * 16], SA);
#pragma unroll
                for (int j = 0; j < 2; j++) {
                    wmma::mma_sync(acc[i][j], fah, fbh[j], acc[i][j]);
                    wmma::mma_sync(acc[i][j], fah, fbl[j], acc[i][j]);
                    wmma::mma_sync(acc[i][j], fal, fbh[j], acc[i][j]);
                }
            }
        }
    }

    // ---- epilogue: direct global stores, fragment-granularity N guard ----
#pragma unroll
    for (int i = 0; i < 4; i++)
#pragma unroll
        for (int j = 0; j < 2; j++) {
            int gm = row0 + wm * 64 + i * 16;
            int gn = col0 + wn * 32 + j * 16;
            if (gn + 16 <= N)
                wmma::store_matrix_sync(C + (long)gm * ldc + gn, acc[i][j],
                                        ldc, wmma::mem_row_major);
        }
}

// ---------------- elementwise / small kernels ----------------
__global__ void embed_kernel(const int* __restrict__ ids,
                             const float* __restrict__ emb)
{
    int row = blockIdx.x;
    int id = ids[row];
    for (int c = threadIdx.x; c < D_MODEL; c += blockDim.x)
        g_x[row * D_MODEL + c] = emb[(long)id * D_MODEL + c];
}

__global__ void rmsnorm_kernel(const float* __restrict__ x,
                               const float* __restrict__ w,
                               float* __restrict__ out)
{
    __shared__ float red[256];
    int row = blockIdx.x;
    const float* xr = x + row * D_MODEL;
    float s = 0.0f;
    for (int c = threadIdx.x; c < D_MODEL; c += blockDim.x) {
        float v = xr[c];
        s += v * v;
    }
    red[threadIdx.x] = s;
    __syncthreads();
    for (int off = 128; off > 0; off >>= 1) {
        if (threadIdx.x < off) red[threadIdx.x] += red[threadIdx.x + off];
        __syncthreads();
    }
    float scale = rsqrtf(red[0] / (float)D_MODEL + 1e-5f);
    for (int c = threadIdx.x; c < D_MODEL; c += blockDim.x)
        out[row * D_MODEL + c] = xr[c] * scale * w[c];
}

__global__ void conv_silu_kernel(const float* __restrict__ cw,
                                 const float* __restrict__ cb)
{
    int i = blockIdx.x * blockDim.x + threadIdx.x;
    if (i >= M_ROWS * D_INNER) return;
    int row = i / D_INNER;
    int d = i % D_INNER;
    int b = row / L_SEQ;
    int l = row % L_SEQ;
    float acc = cb[d];
#pragma unroll
    for (int k = 0; k < D_CONV; k++) {
        int ll = l + k - (D_CONV - 1);
        if (ll >= 0)
            acc = fmaf(g_xz[(long)(b * L_SEQ + ll) * (2 * D_INNER) + d],
                       cw[d * D_CONV + k], acc);
    }
    float sg = 1.0f / (1.0f + __expf(-acc));
    g_xi[i] = acc * sg;
}

__global__ void bias_softplus_kernel(const float* __restrict__ bias)
{
    int i = blockIdx.x * blockDim.x + threadIdx.x;
    if (i >= M_ROWS * D_INNER) return;
    int d = i % D_INNER;
    float v = g_delta[i] + bias[d];
    float r = (v > 30.0f) ? v : log1pf(__expf(v));
    g_delta[i] = r;
}

__global__ void residual_add_kernel(void)
{
    int i = blockIdx.x * blockDim.x + threadIdx.x;
    if (i < M_ROWS * D_MODEL) g_x[i] += g_h[i];
}

// ---------------- selective scan: chunked parallel prefix version ----------
// Block = one (b,d) channel. 256 threads = 16 chunks (c) x 16 states (n),
// tid = c*16 + n. Both s (cumsum of clipped dt*A) and P (cumsum of
// dt*u*B/(exp(s)+eps)) are prefix sums -> 3 passes of 64 serial steps each
// with chunk offsets exchanged through smem, instead of one 1024-step chain.
__global__ __launch_bounds__(256)
void scan_kernel(const float* __restrict__ A_log,
                 const float* __restrict__ Dp)
{
    __shared__ float sTot[16][17];
    __shared__ float pTot[16][17];

    const int tid = threadIdx.x;
    const int c = tid >> 4;        // chunk index 0..15
    const int n = tid & 15;        // state index
    const int bd = blockIdx.x;     // 0 .. B_SZ*D_INNER-1
    const int b = bd / D_INNER;
    const int d = bd % D_INNER;

    const float A_dn = -__expf(A_log[d * D_STATE + n]);
    const int CH = L_SEQ / 16;     // 64
    const long rowbase = (long)b * L_SEQ + (long)c * CH;
    const int lg0 = c * CH;

    // ---- pass 1: chunk-local cumsum totals of a ----
    float sloc = 0.0f;
    for (int i = 0; i < CH; i++) {
        float dt = g_delta[(rowbase + i) * D_INNER + d];
        float a = fmaxf(dt * A_dn, -20.0f);
        if (lg0 + i > 0) sloc += a;
    }
    sTot[n][c] = sloc;
    __syncthreads();
    float soff = 0.0f;
#pragma unroll
    for (int cc = 0; cc < 16; cc++)
        if (cc < c) soff += sTot[n][cc];

    // ---- pass 2: chunk-local cumsum totals of w ----
    sloc = 0.0f;
    float Ploc = 0.0f;
    for (int i = 0; i < CH; i++) {
        long row = rowbase + i;
        float dt = g_delta[row * D_INNER + d];
        float u  = g_xi[row * D_INNER + d];
        float Bn = g_xdbl[row * XDBL_COLS + DT_RANK + n];
        float a = fmaxf(dt * A_dn, -20.0f);
        if (lg0 + i > 0) sloc += a;
        float e = __expf(soff + sloc);
        Ploc += __fdividef(dt * u * Bn, e + 1e-12f);
    }
    pTot[n][c] = Ploc;
    __syncthreads();
    float Poff = 0.0f;
#pragma unroll
    for (int cc = 0; cc < 16; cc++)
        if (cc < c) Poff += pTot[n][cc];

    const float Dd = Dp[d];

    // ---- pass 3: final values + y reduction over n + gate ----
    sloc = 0.0f;
    Ploc = 0.0f;
    for (int i = 0; i < CH; i++) {
        long row = rowbase + i;
        float dt = g_delta[row * D_INNER + d];
        float u  = g_xi[row * D_INNER + d];
        float Bn = g_xdbl[row * XDBL_COLS + DT_RANK + n];
        float Cn = g_xdbl[row * XDBL_COLS + DT_RANK + D_STATE + n];
        float a = fmaxf(dt * A_dn, -20.0f);
        if (lg0 + i > 0) sloc += a;
        float e = __expf(soff + sloc);
        Ploc += __fdividef(dt * u * Bn, e + 1e-12f);
        float x = (Poff + Ploc) * e;
        float yp = x * Cn;
#pragma unroll
        for (int off = 8; off >= 1; off >>= 1)
            yp += __shfl_xor_sync(0xffffffffu, yp, off, 16);
        if (n == 0) {
            float r = g_xz[row * (2 * D_INNER) + D_INNER + d];
            float sr = r / (1.0f + __expf(-r));
            g_y[row * D_INNER + d] = (yp + u * Dd) * sr;
        }
    }
}

// ---------------- host side ----------------
static inline void* sym(const void* s)
{
    void* p = nullptr;
    cudaGetSymbolAddress(&p, s);
    return p;
}

extern "C" void kernel_launch(void* const* d_in, const int* in_sizes, int n_in,
                              void* d_out, int out_size)
{
    const int*   input_ids = (const int*)  d_in[0];
    const float* embedding = (const float*)d_in[1];
    const float* rms_w     = (const float*)d_in[2];
    const float* in_proj_w = (const float*)d_in[3];
    const float* conv_w    = (const float*)d_in[4];
    const float* conv_b    = (const float*)d_in[5];
    const float* x_proj_w  = (const float*)d_in[6];
    const float* dt_proj_w = (const float*)d_in[7];
    const float* dt_proj_b = (const float*)d_in[8];
    const float* A_log     = (const float*)d_in[9];
    const float* D_param   = (const float*)d_in[10];
    const float* out_proj_w= (const float*)d_in[11];
    const float* norm_f_w  = (const float*)d_in[12];
    const float* head_w    = (const float*)d_in[13];
    float* out = (float*)d_out;

    float* px     = (float*)sym(g_x);
    float* ph     = (float*)sym(g_h);
    float* pxz    = (float*)sym(g_xz);
    float* pxi    = (float*)sym(g_xi);
    float* pxdbl  = (float*)sym(g_xdbl);
    float* pdelta = (float*)sym(g_delta);
    float* py     = (float*)sym(g_y);

    embed_kernel<<<M_ROWS, 256>>>(input_ids, embedding);

    for (int i = 0; i < N_LAYER; i++) {
        const float* rw  = rms_w     + (long)i * D_MODEL;
        const float* iw  = in_proj_w + (long)i * D_MODEL * 2 * D_INNER;
        const float* cw  = conv_w    + (long)i * D_INNER * D_CONV;
        const float* cb  = conv_b    + (long)i * D_INNER;
        const float* xpw = x_proj_w  + (long)i * D_INNER * XDBL_COLS;
        const float* dtw = dt_proj_w + (long)i * DT_RANK * D_INNER;
        const float* dtb = dt_proj_b + (long)i * D_INNER;
        const float* al  = A_log     + (long)i * D_INNER * D_STATE;
        const float* dp  = D_param   + (long)i * D_INNER;
        const float* ow  = out_proj_w+ (long)i * D_INNER * D_MODEL;

        // 1. h = rmsnorm(x)
        rmsnorm_kernel<<<M_ROWS, 256>>>(px, rw, ph);

        // 2. xz = h @ in_w  [2048 x 3072 x 768]
        wmma_gemm<<<dim3(2 * D_INNER / 128, M_ROWS / 128), 256>>>(
            M_ROWS, 2 * D_INNER, D_MODEL, ph, D_MODEL, iw, 2 * D_INNER,
            pxz, 2 * D_INNER);

        // 3. xi = silu(conv(xz[:, :1536]))
        conv_silu_kernel<<<(M_ROWS * D_INNER + 255) / 256, 256>>>(cw, cb);

        // 4. x_dbl = xi @ xp_w  [2048 x 80 x 1536]
        wmma_gemm<<<dim3(1, M_ROWS / 128), 256>>>(
            M_ROWS, XDBL_COLS, D_INNER, pxi, D_INNER, xpw, XDBL_COLS,
            pxdbl, XDBL_COLS);

        // 5. delta_raw = x_dbl[:, :48] @ dt_w  [2048 x 1536 x 48]
        wmma_gemm<<<dim3(D_INNER / 128, M_ROWS / 128), 256>>>(
            M_ROWS, D_INNER, DT_RANK, pxdbl, XDBL_COLS, dtw, D_INNER,
            pdelta, D_INNER);

        // 6. delta = softplus(delta_raw + dt_b)
        bias_softplus_kernel<<<(M_ROWS * D_INNER + 255) / 256, 256>>>(dtb);

        // 7. selective scan + gating -> g_y
        scan_kernel<<<B_SZ * D_INNER, 256>>>(al, dp);

        // 8. h_tmp = y @ out_w  [2048 x 768 x 1536]
        wmma_gemm<<<dim3(D_MODEL / 128, M_ROWS / 128), 256>>>(
            M_ROWS, D_MODEL, D_INNER, py, D_INNER, ow, D_MODEL,
            ph, D_MODEL);

        // 9. x += h_tmp
        residual_add_kernel<<<(M_ROWS * D_MODEL + 255) / 256, 256>>>();
    }

    // final rmsnorm + head
    rmsnorm_kernel<<<M_ROWS, 256>>>(px, norm_f_w, ph);
    wmma_gemm<<<dim3(1, M_ROWS / 128), 256>>>(
        M_ROWS, N_MELS, D_MODEL, ph, D_MODEL, head_w, N_MELS,
        out, N_MELS);
}